// round 8
// baseline (speedup 1.0000x reference)
#include <cuda_runtime.h>

// LiquidNeuralNetwork B=256,S=4096,I=32,H=64,O=1 — v8:
// R6 scan structure (2 chains/CTA, 64 thr/chain, named bars) with ALL input
// projection work removed from the scan and materialized to gmem scratch.
//
//   Wc' = (1/tau) * (W_ih@W_in),  cb' = (1/tau)*(bias + W_ih@b_in)   [precompute]
//   ie'[b,t,:] = x[b,t,:]@Wc'^T + cb'                                 [ie_kernel]
//   h_t+1 = (1-1/tau)*h_t + tanh(h_t)@((1/tau)*W_hh)^T + ie'_t        [scan]
//   out_t = tanh(h_t+1)@W_out^T + b_out
//
// Scan: thread j owns hidden unit j; pre-scaled W_hh row resident (32 f32x2).
// Serial path/step: bar -> 8 LDS.128 -> 32 FFMA2 (ie' seed pre-packed into
// acc) -> reduce -> fma -> tanh.approx -> STS. ie' streamed via depth-4
// per-thread LDG pipeline (coalesced 128B/warp/step).

#define NB   256
#define SEQ  4096
#define NI   32
#define NH   64
#define TC   64
#define NC   (SEQ / TC)
#define RS   68            // ring row stride (floats): rows 16B-aligned

typedef unsigned long long u64;

__device__ __forceinline__ float2 upk2(u64 v) {
    float2 f; asm("mov.b64 {%0,%1}, %2;" : "=f"(f.x), "=f"(f.y) : "l"(v)); return f;
}
__device__ __forceinline__ u64 pk2(float lo, float hi) {
    u64 r; asm("mov.b64 %0, {%1,%2};" : "=l"(r) : "f"(lo), "f"(hi)); return r;
}
__device__ __forceinline__ u64 fma2(u64 a, u64 b, u64 c) {
    u64 d; asm("fma.rn.f32x2 %0, %1, %2, %3;" : "=l"(d) : "l"(a), "l"(b), "l"(c)); return d;
}
__device__ __forceinline__ u64 add2(u64 a, u64 b) {
    u64 d; asm("add.rn.f32x2 %0, %1, %2;" : "=l"(d) : "l"(a), "l"(b)); return d;
}
__device__ __forceinline__ float tanh_fast(float x) {
    float y; asm("tanh.approx.f32 %0, %1;" : "=f"(y) : "f"(x)); return y;
}
__device__ __forceinline__ void chain_bar(int ch) {
    asm volatile("bar.sync %0, 64;" :: "r"(1 + ch) : "memory");
}

__device__ float g_Wc[NH * NI];       // pre-scaled by 1/tau
__device__ float g_cbias[NH];         // pre-scaled by 1/tau
__device__ float g_ie[(size_t)NB * SEQ * NH + 4 * NH];   // +4 rows: prefetch overrun pad

// Wc'[g][i] = invt_g * sum_h W_ih[g][h]*W_in[h][i];  cb'[g] = invt_g*(bias+W_ih@b_in)[g]
__global__ __launch_bounds__(32) void precompute_kernel(
    const float* __restrict__ W_in, const float* __restrict__ b_in,
    const float* __restrict__ W_ih, const float* __restrict__ bias,
    const float* __restrict__ tau)
{
    const int g = blockIdx.x;      // 64 blocks
    const int i = threadIdx.x;     // 32 lanes
    const float invt = 1.0f / tau[g];

    float s0 = 0.f, s1 = 0.f;
#pragma unroll 8
    for (int h = 0; h < NH; h += 2) {
        s0 += W_ih[g * NH + h + 0] * W_in[(h + 0) * NI + i];
        s1 += W_ih[g * NH + h + 1] * W_in[(h + 1) * NI + i];
    }
    g_Wc[g * NI + i] = (s0 + s1) * invt;

    // cbias: lanes split h = i, i+32
    float p = W_ih[g * NH + i] * b_in[i] + W_ih[g * NH + i + 32] * b_in[i + 32];
#pragma unroll
    for (int m = 16; m > 0; m >>= 1) p += __shfl_xor_sync(0xFFFFFFFFu, p, m);
    if (i == 0) g_cbias[g] = (bias[g] + p) * invt;
}

// ie'[b][t][j] = x[b,t,:].Wc'[j,:] + cb'[j].  128-thread CTAs, 128-step tiles.
#define TT 128
__global__ __launch_bounds__(128) void ie_kernel(const float* __restrict__ x)
{
    __shared__ __align__(16) float sx[TT * NI];     // 16 KB x tile
    __shared__ __align__(16) float swc[NH * NI];    // 8 KB  Wc'
    __shared__ float scb[NH];

    const int tid = threadIdx.x;
    const int b   = blockIdx.y;
    const int t0  = blockIdx.x * TT;

    const float4* xg = (const float4*)(x + ((size_t)b * SEQ + t0) * NI);
#pragma unroll
    for (int q = 0; q < 8; q++) ((float4*)sx)[q * 128 + tid] = xg[q * 128 + tid];
#pragma unroll
    for (int q = 0; q < 4; q++)
        ((float4*)swc)[q * 128 + tid] = ((const float4*)g_Wc)[q * 128 + tid];
    if (tid < NH) scb[tid] = g_cbias[tid];
    __syncthreads();

    // Own time-row in packed registers (16 u64)
    u64 xr[NI / 2];
    {
        const ulonglong2* p = (const ulonglong2*)(sx + tid * NI);
#pragma unroll
        for (int m = 0; m < 8; m++) { ulonglong2 v = p[m]; xr[2 * m] = v.x; xr[2 * m + 1] = v.y; }
    }

    float4* og = (float4*)(g_ie + ((size_t)b * SEQ + t0 + tid) * NH);
#pragma unroll 2
    for (int j4 = 0; j4 < NH / 4; j4++) {
        float4 buf;
        float* bp = &buf.x;
#pragma unroll
        for (int jj = 0; jj < 4; jj++) {
            const int j = 4 * j4 + jj;
            const ulonglong2* w = (const ulonglong2*)(swc + j * NI);  // LDS broadcast
            u64 a0 = 0ull, a1 = 0ull;
#pragma unroll
            for (int m = 0; m < 8; m++) {
                ulonglong2 v = w[m];
                a0 = fma2(xr[2 * m + 0], v.x, a0);
                a1 = fma2(xr[2 * m + 1], v.y, a1);
            }
            float2 f = upk2(add2(a0, a1));
            bp[jj] = (f.x + f.y) + scb[j];
        }
        og[j4] = buf;
    }
}

__global__ __launch_bounds__(128) void lnn_scan_kernel(
    const float* __restrict__ W_hh,
    const float* __restrict__ tau,
    const float* __restrict__ W_out,
    const float* __restrict__ b_out,
    float* __restrict__ out)
{
    __shared__ __align__(16) float ring[2][(TC + 1) * RS];   // tanh history
    __shared__ float swo[2][NH];

    const int tid = threadIdx.x;
    const int ch  = tid >> 6;          // independent chain (no cross-chain sync)
    const int lid = tid & 63;          // hidden unit owned
    const int b   = blockIdx.x * 2 + ch;

    const float invt  = 1.0f / tau[lid];
    const float alpha = 1.0f - invt;

    // Resident pre-scaled W_hh row: 32 f32x2 regs
    u64 Whh2[NH / 2];
    {
        const float* wr = W_hh + lid * NH;
#pragma unroll
        for (int m = 0; m < NH / 2; m++)
            Whh2[m] = pk2(wr[2 * m] * invt, wr[2 * m + 1] * invt);
    }
    const float bo = b_out[0];
    swo[ch][lid] = W_out[lid];

    // ie' stream: 1 float / thread / step, coalesced 128B per warp.
    const float* iep = g_ie + (size_t)b * SEQ * NH + lid;
    u64 seed[4];                       // pre-packed (ie', 0) accumulator seeds
#pragma unroll
    for (int d = 0; d < 4; d++) seed[d] = pk2(iep[d * NH], 0.0f);
    const float* iah = iep + 4 * NH;   // refill cursor (pad rows absorb overrun)

    float h = 0.f;
    ring[ch][lid] = 0.f;               // row 0 = tanh(h0) = 0
    float* outb = out + (size_t)b * SEQ;
    chain_bar(ch);                     // row 0 / swo visible

#pragma unroll 1
    for (int c = 0; c < NC; c++) {
#pragma unroll 4
        for (int tt = 0; tt < TC; tt++) {
            chain_bar(ch);             // ring row tt visible to both warps

            // hh dot (pre-scaled): 32 FFMA2, 4 chains; ie'+bias pre-seeded.
            u64 a0 = seed[tt & 3], a1 = 0ull, a2 = 0ull, a3 = 0ull;
            const ulonglong2* t2 = (const ulonglong2*)(ring[ch] + tt * RS);
#pragma unroll
            for (int m = 0; m < 16; m += 2) {
                ulonglong2 v = t2[m];
                ulonglong2 w = t2[m + 1];
                a0 = fma2(v.x, Whh2[2 * m + 0], a0);
                a1 = fma2(v.y, Whh2[2 * m + 1], a1);
                a2 = fma2(w.x, Whh2[2 * m + 2], a2);
                a3 = fma2(w.y, Whh2[2 * m + 3], a3);
            }
            // Refill seed for step t+4 (off the dependency chain)
            seed[tt & 3] = pk2(*iah, 0.0f);
            iah += NH;

            a0 = add2(a0, a1); a2 = add2(a2, a3); a0 = add2(a0, a2);
            float2 f = upk2(a0);
            h = fmaf(h, alpha, f.x + f.y);             // Euler (invt pre-folded)
            ring[ch][(tt + 1) * RS + lid] = tanh_fast(h);
        }
        chain_bar(ch);                 // rows 1..TC complete

        // Output head: thread lid -> out[c*TC+lid] from ring row lid+1.
        {
            const float* row = ring[ch] + (lid + 1) * RS;
            const float* wo  = swo[ch];
            float o0 = bo, o1 = 0.f, o2 = 0.f, o3 = 0.f;
#pragma unroll
            for (int k = 0; k < NH; k += 4) {
                o0 += row[k + 0] * wo[k + 0];
                o1 += row[k + 1] * wo[k + 1];
                o2 += row[k + 2] * wo[k + 2];
                o3 += row[k + 3] * wo[k + 3];
            }
            outb[c * TC + lid] = (o0 + o1) + (o2 + o3);
        }
        ring[ch][lid] = ring[ch][TC * RS + lid];   // carry row TC -> row 0
        // Next chunk's first chain_bar orders these writes before reads.
    }
}

extern "C" void kernel_launch(void* const* d_in, const int* in_sizes, int n_in,
                              void* d_out, int out_size)
{
    const float* x     = (const float*)d_in[0];
    const float* W_in  = (const float*)d_in[1];
    const float* b_in  = (const float*)d_in[2];
    const float* W_hh  = (const float*)d_in[3];
    const float* W_ih  = (const float*)d_in[4];
    const float* bias  = (const float*)d_in[5];
    const float* tau   = (const float*)d_in[6];
    const float* W_out = (const float*)d_in[7];
    const float* b_out = (const float*)d_in[8];
    float* out = (float*)d_out;

    precompute_kernel<<<NH, 32>>>(W_in, b_in, W_ih, bias, tau);
    dim3 ie_grid(SEQ / TT, NB);
    ie_kernel<<<ie_grid, 128>>>(x);
    lnn_scan_kernel<<<NB / 2, 128>>>(W_hh, tau, W_out, b_out, out);
}

// round 9
// speedup vs baseline: 2.6006x; 2.6006x over previous
#include <cuda_runtime.h>

// LiquidNeuralNetwork B=256,S=4096,I=32,H=64,O=1 — v9:
// R6 scan skeleton + precomputed ie' delivered by CHUNK-staged smem
// (no per-step LDG on the serial path — the R7/R8 failure mode).
//
//   Wc' = (1/tau)*(W_ih@W_in),  cb' = (1/tau)*(bias + W_ih@b_in)
//   ie'[b,t,:] = x[b,t,:]@Wc'^T + cb'                       [ie_kernel, gmem]
//   h_t+1 = (1-1/tau)*h_t + tanh(h_t)@((1/tau)*W_hh)^T + ie'_t
//   out_t = tanh(h_t+1)@W_out^T + b_out
//
// Scan: 128 CTAs, 2 independent chains/CTA (named bar.sync(1+ch,64)), thread
// j owns hidden unit j, pre-scaled W_hh row resident as 32 f32x2 regs.
// Per step: bar -> LDS.32 ie (latency hidden under dot) -> 8 LDS.128 ring ->
// 32 FFMA2 -> reduce -> fma -> tanh.approx -> STS. ie chunk prefetched a full
// chunk ahead into registers (8 LDG.128), staged to smem at chunk top.

#define NB   256
#define SEQ  4096
#define NI   32
#define NH   64
#define TC   32
#define NC   (SEQ / TC)
#define RS   68            // ring row stride (floats): rows 16B-aligned

typedef unsigned long long u64;

__device__ __forceinline__ float2 upk2(u64 v) {
    float2 f; asm("mov.b64 {%0,%1}, %2;" : "=f"(f.x), "=f"(f.y) : "l"(v)); return f;
}
__device__ __forceinline__ u64 pk2(float lo, float hi) {
    u64 r; asm("mov.b64 %0, {%1,%2};" : "=l"(r) : "f"(lo), "f"(hi)); return r;
}
__device__ __forceinline__ u64 fma2(u64 a, u64 b, u64 c) {
    u64 d; asm("fma.rn.f32x2 %0, %1, %2, %3;" : "=l"(d) : "l"(a), "l"(b), "l"(c)); return d;
}
__device__ __forceinline__ u64 add2(u64 a, u64 b) {
    u64 d; asm("add.rn.f32x2 %0, %1, %2;" : "=l"(d) : "l"(a), "l"(b)); return d;
}
__device__ __forceinline__ float tanh_fast(float x) {
    float y; asm("tanh.approx.f32 %0, %1;" : "=f"(y) : "f"(x)); return y;
}
__device__ __forceinline__ void chain_bar(int ch) {
    asm volatile("bar.sync %0, 64;" :: "r"(1 + ch) : "memory");
}

__device__ float g_Wc[NH * NI];       // pre-scaled by 1/tau
__device__ float g_cbias[NH];         // pre-scaled by 1/tau
__device__ float g_ie[(size_t)NB * SEQ * NH];

__global__ __launch_bounds__(32) void precompute_kernel(
    const float* __restrict__ W_in, const float* __restrict__ b_in,
    const float* __restrict__ W_ih, const float* __restrict__ bias,
    const float* __restrict__ tau)
{
    const int g = blockIdx.x;      // 64 blocks
    const int i = threadIdx.x;     // 32 lanes
    const float invt = 1.0f / tau[g];

    float s0 = 0.f, s1 = 0.f;
#pragma unroll 8
    for (int h = 0; h < NH; h += 2) {
        s0 += W_ih[g * NH + h + 0] * W_in[(h + 0) * NI + i];
        s1 += W_ih[g * NH + h + 1] * W_in[(h + 1) * NI + i];
    }
    g_Wc[g * NI + i] = (s0 + s1) * invt;

    float p = W_ih[g * NH + i] * b_in[i] + W_ih[g * NH + i + 32] * b_in[i + 32];
#pragma unroll
    for (int m = 16; m > 0; m >>= 1) p += __shfl_xor_sync(0xFFFFFFFFu, p, m);
    if (i == 0) g_cbias[g] = (bias[g] + p) * invt;
}

// ie'[b][t][j] = x[b,t,:].Wc'[j,:] + cb'[j].  128-thread CTAs, 128-step tiles.
#define TT 128
__global__ __launch_bounds__(128) void ie_kernel(const float* __restrict__ x)
{
    __shared__ __align__(16) float sx[TT * NI];
    __shared__ __align__(16) float swc[NH * NI];
    __shared__ float scb[NH];

    const int tid = threadIdx.x;
    const int b   = blockIdx.y;
    const int t0  = blockIdx.x * TT;

    const float4* xg = (const float4*)(x + ((size_t)b * SEQ + t0) * NI);
#pragma unroll
    for (int q = 0; q < 8; q++) ((float4*)sx)[q * 128 + tid] = xg[q * 128 + tid];
#pragma unroll
    for (int q = 0; q < 4; q++)
        ((float4*)swc)[q * 128 + tid] = ((const float4*)g_Wc)[q * 128 + tid];
    if (tid < NH) scb[tid] = g_cbias[tid];
    __syncthreads();

    u64 xr[NI / 2];
    {
        const ulonglong2* p = (const ulonglong2*)(sx + tid * NI);
#pragma unroll
        for (int m = 0; m < 8; m++) { ulonglong2 v = p[m]; xr[2 * m] = v.x; xr[2 * m + 1] = v.y; }
    }

    float4* og = (float4*)(g_ie + ((size_t)b * SEQ + t0 + tid) * NH);
#pragma unroll 2
    for (int j4 = 0; j4 < NH / 4; j4++) {
        float4 buf;
        float* bp = &buf.x;
#pragma unroll
        for (int jj = 0; jj < 4; jj++) {
            const int j = 4 * j4 + jj;
            const ulonglong2* w = (const ulonglong2*)(swc + j * NI);
            u64 a0 = 0ull, a1 = 0ull;
#pragma unroll
            for (int m = 0; m < 8; m++) {
                ulonglong2 v = w[m];
                a0 = fma2(xr[2 * m + 0], v.x, a0);
                a1 = fma2(xr[2 * m + 1], v.y, a1);
            }
            float2 f = upk2(add2(a0, a1));
            bp[jj] = (f.x + f.y) + scb[j];
        }
        og[j4] = buf;
    }
}

__global__ __launch_bounds__(128) void lnn_scan_kernel(
    const float* __restrict__ W_hh,
    const float* __restrict__ tau,
    const float* __restrict__ W_out,
    const float* __restrict__ b_out,
    float* __restrict__ out)
{
    __shared__ __align__(16) float ring [2][(TC + 1) * RS];  // tanh history
    __shared__ __align__(16) float sh_ie[2][TC * NH];        // ie' chunk stage
    __shared__ float swo[2][NH];

    const int tid = threadIdx.x;
    const int ch  = tid >> 6;          // independent chain (no cross-chain sync)
    const int lid = tid & 63;          // hidden unit owned
    const int b   = blockIdx.x * 2 + ch;

    const float invt  = 1.0f / tau[lid];
    const float alpha = 1.0f - invt;

    // Resident pre-scaled W_hh row: 32 f32x2 regs
    u64 Whh2[NH / 2];
    {
        const float* wr = W_hh + lid * NH;
#pragma unroll
        for (int m = 0; m < NH / 2; m++)
            Whh2[m] = pk2(wr[2 * m] * invt, wr[2 * m + 1] * invt);
    }
    const float bo = b_out[0];
    swo[ch][lid] = W_out[lid];

    // Chunk ie prefetch: 8 float4 / thread (2048 floats = 32 steps x 64 units)
    const float4* ieg = (const float4*)(g_ie + (size_t)b * SEQ * NH);
    float4 pf[8];
#pragma unroll
    for (int q = 0; q < 8; q++) pf[q] = ieg[q * 64 + lid];

    float h = 0.f;
    ring[ch][lid] = 0.f;               // row 0 = tanh(h0) = 0
    float* outb = out + (size_t)b * SEQ;

#pragma unroll 1
    for (int c = 0; c < NC; c++) {
        // Stage ie chunk to smem; prefetch next chunk (full-chunk slack — the
        // R6-proven LDG pattern; never a short-slack LDG between step bars).
#pragma unroll
        for (int q = 0; q < 8; q++) ((float4*)sh_ie[ch])[q * 64 + lid] = pf[q];
        if (c + 1 < NC) {
#pragma unroll
            for (int q = 0; q < 8; q++) pf[q] = ieg[(c + 1) * 512 + q * 64 + lid];
        }

#pragma unroll 4
        for (int tt = 0; tt < TC; tt++) {
            chain_bar(ch);             // ring row tt + (first pass) sh_ie visible

            // ie value first: LDS.32 latency hides under the 32-FFMA2 dot
            const float iev = sh_ie[ch][tt * NH + lid];

            u64 a0 = 0ull, a1 = 0ull, a2 = 0ull, a3 = 0ull;
            const ulonglong2* t2 = (const ulonglong2*)(ring[ch] + tt * RS);
#pragma unroll
            for (int m = 0; m < 16; m += 2) {
                ulonglong2 v = t2[m];
                ulonglong2 w = t2[m + 1];
                a0 = fma2(v.x, Whh2[2 * m + 0], a0);
                a1 = fma2(v.y, Whh2[2 * m + 1], a1);
                a2 = fma2(w.x, Whh2[2 * m + 2], a2);
                a3 = fma2(w.y, Whh2[2 * m + 3], a3);
            }
            a0 = add2(a0, a1); a2 = add2(a2, a3); a0 = add2(a0, a2);
            float2 f = upk2(a0);
            h = fmaf(h, alpha, f.x + (f.y + iev));     // Euler (invt pre-folded)
            ring[ch][(tt + 1) * RS + lid] = tanh_fast(h);
        }
        chain_bar(ch);                 // rows 1..TC complete, sh_ie reads done

        // Output head: thread lid<TC -> out[c*TC+lid] from ring row lid+1.
        if (lid < TC) {
            const float* row = ring[ch] + (lid + 1) * RS;
            const float* wo  = swo[ch];
            float o0 = bo, o1 = 0.f, o2 = 0.f, o3 = 0.f;
#pragma unroll
            for (int k = 0; k < NH; k += 4) {
                o0 += row[k + 0] * wo[k + 0];
                o1 += row[k + 1] * wo[k + 1];
                o2 += row[k + 2] * wo[k + 2];
                o3 += row[k + 3] * wo[k + 3];
            }
            outb[c * TC + lid] = (o0 + o1) + (o2 + o3);
        }
        ring[ch][lid] = ring[ch][TC * RS + lid];   // carry row TC -> row 0
        // Next chunk's first chain_bar orders the carry/sh_ie writes.
    }
}

extern "C" void kernel_launch(void* const* d_in, const int* in_sizes, int n_in,
                              void* d_out, int out_size)
{
    const float* x     = (const float*)d_in[0];
    const float* W_in  = (const float*)d_in[1];
    const float* b_in  = (const float*)d_in[2];
    const float* W_hh  = (const float*)d_in[3];
    const float* W_ih  = (const float*)d_in[4];
    const float* bias  = (const float*)d_in[5];
    const float* tau   = (const float*)d_in[6];
    const float* W_out = (const float*)d_in[7];
    const float* b_out = (const float*)d_in[8];
    float* out = (float*)d_out;

    precompute_kernel<<<NH, 32>>>(W_in, b_in, W_ih, bias, tau);
    dim3 ie_grid(SEQ / TT, NB);
    ie_kernel<<<ie_grid, 128>>>(x);
    lnn_scan_kernel<<<NB / 2, 128>>>(W_hh, tau, W_out, b_out, out);
}